// round 17
// baseline (speedup 1.0000x reference)
#include <cuda_runtime.h>
#include <cuda_bf16.h>
#include <math.h>

// ---------------- problem constants ----------------
#define VOCAB 50257
#define EMBD  32
#define HID   8
#define NB    48     // batch
#define NT    128    // seq
#define NROWS (NB*NT)          // 6144
#define VP    51200            // padded vocab width (400 chunks of 128)
#define VS    16               // vocab splits
#define NCH   400              // chunks of 128 cols
#define CPC   (NCH/VS)         // 25 chunks per CTA

#define LOG2E 1.4426950408889634f
#define LN2   0.6931471805599453f

// ---------------- device scratch (no cudaMalloc allowed) ----------------
__device__ __align__(16) float g_W4[4 * 16 * VP];   // 4 shifted copies of log2e*h2o, padded 0
__device__ __align__(16) float g_Bs[NB * VP];       // per-b shifted log2e*bias, pad -1e30
__device__ __align__(16) float g_E [NB * NT * HID]; // E[b][t][j] = emb @ i2h[:32]
__device__ __align__(16) float g_H [NB * NT * 16];  // H[b][t][0:8]=hf_used, [8:16]=hb_used
__device__ float g_Zpart[NROWS * VS];

typedef unsigned long long u64;

// ---------------- f32x2 helpers (sm_103a packed fp32) ----------------
__device__ __forceinline__ u64 pk2(float x) {
    u64 r; asm("mov.b64 %0,{%1,%1};" : "=l"(r) : "f"(x)); return r;
}
__device__ __forceinline__ u64 f2fma(u64 a, u64 b, u64 c) {
    u64 d; asm("fma.rn.f32x2 %0,%1,%2,%3;" : "=l"(d) : "l"(a), "l"(b), "l"(c)); return d;
}
__device__ __forceinline__ float2 up2(u64 a) {
    float2 f; asm("mov.b64 {%0,%1},%2;" : "=f"(f.x), "=f"(f.y) : "l"(a)); return f;
}
__device__ __forceinline__ float ex2f(float x) {
    float r; asm("ex2.approx.f32 %0, %1;" : "=f"(r) : "f"(x)); return r;
}
__device__ __forceinline__ void cp16(void* dst, const void* src) {
    unsigned saddr = (unsigned)__cvta_generic_to_shared(dst);
    asm volatile("cp.async.cg.shared.global [%0], [%1], 16;" :: "r"(saddr), "l"(src));
}

// ---------------- fused prep: shifted/padded log2e*W copies + log2e*bias ----------------
#define W_TOTAL (4 * 16 * VP)
#define B_TOTAL (NB * VP)
__global__ void prep_kernel(const float* __restrict__ h2o,
                            const float* __restrict__ bias) {
    int idx = blockIdx.x * blockDim.x + threadIdx.x;
    if (idx < W_TOTAL) {
        int s = idx / (16 * VP);
        int rem = idx - s * (16 * VP);
        int k = rem / VP;
        int i = rem - k * VP;
        int lo = i - s;
        float v = 0.0f;
        if (lo >= 0 && lo < VOCAB) v = LOG2E * h2o[k * VOCAB + lo];
        g_W4[idx] = v;
    } else {
        int j = idx - W_TOTAL;
        if (j >= B_TOTAL) return;
        int b = j / VP;
        int i = j - b * VP;
        int s = b & 3;
        int lo = i - s;
        float v = -1e30f;                 // ex2 -> 0 on pads
        if (lo >= 0 && lo < VOCAB) v = LOG2E * bias[b * VOCAB + lo];
        g_Bs[j] = v;
    }
}

// ---------------- E = gather(we, ids) @ i2h[0:32,:] ----------------
__global__ void emb_kernel(const int* __restrict__ ids,
                           const float* __restrict__ we,
                           const float* __restrict__ i2h) {
    int gid = blockIdx.x * blockDim.x + threadIdx.x;
    if (gid >= NROWS * HID) return;
    int r = gid >> 3;
    int j = gid & 7;
    int t = r / NB;
    int b = r - t * NB;
    int id = ids[r];
    const float* wr = we + (long)id * EMBD;
    float acc = 0.0f;
#pragma unroll
    for (int k = 0; k < EMBD; k++)
        acc += __ldg(wr + k) * __ldg(i2h + k * HID + j);
    g_E[((b << 7) + t) * HID + j] = acc;
}

// ---------------- RNN scans: 96 warps (48 b x 2 dir), tree-sum step ----------------
__global__ void rnn_kernel(const float* __restrict__ i2h,
                           const float* __restrict__ h0f,
                           const float* __restrict__ h0b) {
    int wg = blockIdx.x * (blockDim.x >> 5) + (threadIdx.x >> 5);
    if (wg >= 2 * NB) return;
    int lane = threadIdx.x & 31;
    int j = lane & 7;
    int dir = (wg >= NB) ? 1 : 0;
    int b = wg - dir * NB;

    float U[HID];
#pragma unroll
    for (int kk = 0; kk < HID; kk++)
        U[kk] = i2h[(EMBD + kk) * HID + j];

    float h = dir ? h0b[b * HID + j] : h0f[b * HID + j];
    int t_first = dir ? (NT - 1) : 0;
    float e_cur = g_E[((b << 7) + t_first) * HID + j];

    for (int step = 0; step < NT; step++) {
        int t = dir ? (NT - 1 - step) : step;
        float e_next = 0.0f;
        if (step + 1 < NT) {
            int tn = dir ? (NT - 2 - step) : (step + 1);
            e_next = g_E[((b << 7) + tn) * HID + j];
        }
        if (lane < HID)
            g_H[((b << 7) + t) * 16 + dir * HID + j] = h;
        float p0 = __shfl_sync(0xFFFFFFFFu, h, 0) * U[0];
        float p1 = __shfl_sync(0xFFFFFFFFu, h, 1) * U[1];
        float p2 = __shfl_sync(0xFFFFFFFFu, h, 2) * U[2];
        float p3 = __shfl_sync(0xFFFFFFFFu, h, 3) * U[3];
        float p4 = __shfl_sync(0xFFFFFFFFu, h, 4) * U[4];
        float p5 = __shfl_sync(0xFFFFFFFFu, h, 5) * U[5];
        float p6 = __shfl_sync(0xFFFFFFFFu, h, 6) * U[6];
        float p7 = __shfl_sync(0xFFFFFFFFu, h, 7) * U[7];
        float acc = (((p0 + p1) + (p2 + p3)) + ((p4 + p5) + (p6 + p7))) + e_cur;
        float ex = __expf(2.0f * acc);
        h = (ex - 1.0f) * __fdividef(1.0f, ex + 1.0f);
        e_cur = e_next;
    }
}

// ---------------- main passes ----------------
// grid: 48 b * 16 vs = 768 CTAs, 256 threads, OCC 1 (reg budget 255 -> no spill).
// CTA covers ALL 128 t-rows of one b. Warp owns 16 rows; lane owns 4 cols/chunk.
// Per warp-chunk: fma 128 SM-cyc vs L1 96 -> fma-bound (h broadcasts amortized 16x).
template<int PASS>
__global__ __launch_bounds__(256, 1) void pass_kernel(float* __restrict__ out) {
    int bx = blockIdx.x;
    int vs = bx & (VS - 1);
    int b = bx >> 4;
    int s = b & 3;

    const float* __restrict__ W  = g_W4 + s * (16 * VP);
    const float* __restrict__ Bp = g_Bs + b * VP;

    __shared__ __align__(16) float smw[3][16 * 128];  // 3 x 8KB W chunk buffers
    __shared__ __align__(16) u64 smh[128 * 16];       // (h,h) packed per row,k (16KB)
    __shared__ u64 smlz[128];                         // (-lz,-lz) packed

    int tid = threadIdx.x;

    // prefetch of one W chunk: 512 float4; each thread copies 2
    auto prefetch = [&](int ci, int buf) {
        int colbase = ((ci << 4) + vs) * 128;
        const float* src = W + colbase;
#pragma unroll
        for (int h = 0; h < 2; h++) {
            int f4 = tid + h * 256;          // 0..511
            int k = f4 >> 5;                 // 32 float4 per k-row
            int c = (f4 & 31) << 2;
            cp16(&smw[buf][k * 128 + c], src + (long)k * VP + c);
        }
        asm volatile("cp.async.commit_group;" ::: "memory");
    };

    prefetch(0, 0);
    prefetch(1, 1);

    for (int i = tid; i < 2048; i += 256)
        smh[i] = pk2(g_H[((b << 7) << 4) + i]);
    if (PASS == 2 && tid < 128) {
        // fused Z-reduction: lz for row tid of batch b
        const float* zp = g_Zpart + (long)((b << 7) + tid) * VS;
        float ssum = 0.0f;
#pragma unroll
        for (int v = 0; v < VS; v++) ssum += zp[v];
        smlz[tid] = pk2(-logf(ssum));
    }

    int warp = tid >> 5, lane = tid & 31;
    int r0 = warp << 4;                               // 16 rows per warp
    float zz[16];
#pragma unroll
    for (int r = 0; r < 16; r++) zz[r] = 0.0f;
    u64 ln2p = pk2(LN2);

    for (int ci = 0; ci < CPC; ci++) {
        int p = ci % 3;
        if (ci < CPC - 1) asm volatile("cp.async.wait_group 1;" ::: "memory");
        else              asm volatile("cp.async.wait_group 0;" ::: "memory");
        __syncthreads();   // chunk ci landed for all threads (covers smh/smlz on ci==0)

        int col = ((ci << 4) + vs) * 128 + (lane << 2);
        ulonglong2 bb = *(const ulonglong2*)(Bp + col);
        u64 a[16][2];
#pragma unroll
        for (int r = 0; r < 16; r++) { a[r][0] = bb.x; a[r][1] = bb.y; }

        const float* wp0 = &smw[p][lane << 2];
#pragma unroll
        for (int kg = 0; kg < 4; kg++) {
            const float* wp = wp0 + (kg << 9);        // kg*4 k-rows * 128
            ulonglong2 w0 = *(const ulonglong2*)(wp);
            ulonglong2 w1 = *(const ulonglong2*)(wp + 128);
            ulonglong2 w2 = *(const ulonglong2*)(wp + 256);
            ulonglong2 w3 = *(const ulonglong2*)(wp + 384);
#pragma unroll
            for (int r = 0; r < 16; r++) {
                const ulonglong2* hp = (const ulonglong2*)&smh[((r0 + r) << 4) + (kg << 2)];
                ulonglong2 h01 = hp[0];
                ulonglong2 h23 = hp[1];
                a[r][0] = f2fma(h01.x, w0.x, a[r][0]);
                a[r][1] = f2fma(h01.x, w0.y, a[r][1]);
                a[r][0] = f2fma(h01.y, w1.x, a[r][0]);
                a[r][1] = f2fma(h01.y, w1.y, a[r][1]);
                a[r][0] = f2fma(h23.x, w2.x, a[r][0]);
                a[r][1] = f2fma(h23.x, w2.y, a[r][1]);
                a[r][0] = f2fma(h23.y, w3.x, a[r][0]);
                a[r][1] = f2fma(h23.y, w3.y, a[r][1]);
            }
        }

#pragma unroll
        for (int r = 0; r < 16; r++) {
            if (PASS == 1) {
                // accumulators are log2-scaled: exp(logit+bias) = 2^acc
                float2 pp = up2(a[r][0]), qq = up2(a[r][1]);
                zz[r] += (ex2f(pp.x) + ex2f(pp.y)) + (ex2f(qq.x) + ex2f(qq.y));
            } else {
                int row = r0 + r;
                u64 lz = smlz[row];
                u64 a0 = f2fma(a[r][0], ln2p, lz);    // ln2*acc - lz
                u64 a1 = f2fma(a[r][1], ln2p, lz);
                long rowbase = (long)(row * NB + b) * VOCAB;
                int lo = col - s;
                float2 pp = up2(a0), qq = up2(a1);
                if (lo >= 0 && lo + 4 <= VOCAB) {
                    // rowbase % 4 == s, lo % 4 == (4-s)%4 -> 16B-aligned store
                    float4 v4 = make_float4(pp.x, pp.y, qq.x, qq.y);
                    __stcs((float4*)(out + rowbase + lo), v4);
                } else {
                    float vals[4] = {pp.x, pp.y, qq.x, qq.y};
#pragma unroll
                    for (int e = 0; e < 4; e++) {
                        int v = lo + e;
                        if (v >= 0 && v < VOCAB) __stcs(out + rowbase + v, vals[e]);
                    }
                }
            }
        }

        if (ci + 2 < CPC) prefetch(ci + 2, (ci + 2) % 3);
    }

    if (PASS == 1) {
#pragma unroll
        for (int r = 0; r < 16; r++) {
            float zr = zz[r];
#pragma unroll
            for (int o = 16; o; o >>= 1) zr += __shfl_xor_sync(0xFFFFFFFFu, zr, o);
            if (lane == 0)
                g_Zpart[((b << 7) + r0 + r) * VS + vs] = zr;
        }
    }
}

// ---------------- launch ----------------
extern "C" void kernel_launch(void* const* d_in, const int* in_sizes, int n_in,
                              void* d_out, int out_size) {
    const int*   ids  = (const int*)  d_in[0];
    const float* we   = (const float*)d_in[1];
    const float* i2h  = (const float*)d_in[2];
    const float* h2o  = (const float*)d_in[3];
    const float* bias = (const float*)d_in[4];
    const float* h0f  = (const float*)d_in[5];
    const float* h0b  = (const float*)d_in[6];
    float* out = (float*)d_out;

    {
        int n = W_TOTAL + B_TOTAL;
        prep_kernel<<<(n + 255) / 256, 256>>>(h2o, bias);       // launch 0
    }
    {
        int n = NROWS * HID;
        emb_kernel<<<(n + 255) / 256, 256>>>(ids, we, i2h);     // launch 1
    }
    rnn_kernel<<<24, 128>>>(i2h, h0f, h0b);                     // launch 2

    pass_kernel<1><<<NB * VS, 256>>>(out);                      // launch 3 (ncu capture slot)
    pass_kernel<2><<<NB * VS, 256>>>(out);                      // launch 4 (lz fused in prologue)
}